// round 1
// baseline (speedup 1.0000x reference)
#include <cuda_runtime.h>

// Problem shape (fixed for this instance)
#define B_ 64
#define S_ 1024
#define L_ 16
#define T_ 32

#define LOG2E 1.4426950408889634f
#define LN2   0.6931471805599453f

// Scratch (static __device__ arrays — allocation-free per harness rules)
__device__ float g_w[B_ * S_ * L_];   // w[b][e][k] = sum_t exp(tr[b,e,k,t])  (4 MB, L2-resident)
__device__ float g_nc[B_ * S_];       // nc[b][e]  = tr[b,e,0,tags[b,e]]

__device__ __forceinline__ float ex2f_(float x) {
    float r; asm("ex2.approx.f32 %0, %1;" : "=f"(r) : "f"(x)); return r;
}
__device__ __forceinline__ float lg2f_(float x) {
    float r; asm("lg2.approx.f32 %0, %1;" : "=f"(r) : "f"(x)); return r;
}

// ---------------------------------------------------------------------------
// Kernel A: memory-bound. One warp per (b,e) pair: computes the 16 per-row
// sums w[k] = sum_t exp(tr[k,t]) over the [L=16, T=32] tile (2 KB), plus the
// numerator gather nc = tr[0, tag]. Also zeroes the output scalar.
// ---------------------------------------------------------------------------
__global__ __launch_bounds__(256) void semicrf_rowsum(
    const float* __restrict__ tr,
    const int*   __restrict__ tags,
    float*       __restrict__ out)
{
    if (blockIdx.x == 0 && threadIdx.x == 0) out[0] = 0.0f;

    const int wid  = (blockIdx.x * 256 + threadIdx.x) >> 5;   // (b*S + e), 0..65535
    const int lane = threadIdx.x & 31;

    const float4* base = reinterpret_cast<const float4*>(tr) + (size_t)wid * 128;
    const int sub = lane >> 3;   // row within the 4-row group covered by one float4 load

    float rs[4];
#pragma unroll
    for (int i = 0; i < 4; i++) {
        // load i covers rows 4i..4i+3; 8 lanes per row, 4 consecutive floats per lane
        float4 v = base[i * 32 + lane];
        float s = ex2f_(v.x * LOG2E) + ex2f_(v.y * LOG2E)
                + ex2f_(v.z * LOG2E) + ex2f_(v.w * LOG2E);
        // reduce across the 8 lanes sharing a row
        s += __shfl_xor_sync(0xffffffffu, s, 1);
        s += __shfl_xor_sync(0xffffffffu, s, 2);
        s += __shfl_xor_sync(0xffffffffu, s, 4);
        rs[i] = s;
    }

    if ((lane & 7) == 0) {
        float* wb = g_w + (size_t)wid * 16;
#pragma unroll
        for (int i = 0; i < 4; i++) wb[i * 4 + sub] = rs[i];
    }

    if (lane == 0) {
        int tag = tags[wid];                       // in [0, 32) per problem setup
        g_nc[wid] = tr[(size_t)wid * 512 + tag];   // row 0 gather
    }
}

// ---------------------------------------------------------------------------
// Kernel B: the sequential scan, linearized. One thread per batch (2 blocks
// of 32 threads so each warp owns its own SM/SMSP). State:
//   z[e] = exp(alpha[e]) * 2^{-C}    (C integer, exact power-of-2 renorm)
//   z[e+1] = sum_k z[e-k] * w[e,k]   — pure FFMA recurrence.
// 16-step unrolled ring window (static register indexing, no moves),
// 4-step double-buffered register prefetch of w rows from L2.
// ---------------------------------------------------------------------------
__global__ __launch_bounds__(32, 1) void semicrf_scan(
    const int* __restrict__ lens,
    float*     __restrict__ out)
{
    const int b = blockIdx.x * 32 + threadIdx.x;   // batch index, 0..63
    const float4* wp  = reinterpret_cast<const float4*>(g_w)  + (size_t)b * (S_ * L_ / 4);
    const float4* ncp = reinterpret_cast<const float4*>(g_nc) + (size_t)b * (S_ / 4);
    const int len = lens[b];

    float zz[16];
    zz[0] = 1.0f;                     // z at e=0: alpha[0]=0
#pragma unroll
    for (int k = 1; k < 16; k++) zz[k] = 0.0f;   // alpha[-k] = -inf

    int   C   = 0;
    float num = 0.0f, den = 0.0f;

    float4 bufA[16], bufB[16];        // 4 steps x 4 float4 each
    float4 ncA, ncB;

    // prologue: load sub-block 0 (steps 0..3)
#pragma unroll
    for (int j2 = 0; j2 < 16; j2++) bufA[j2] = wp[j2];
    ncA = ncp[0];
    ncB = ncA;  // init to silence any path; overwritten before use

    for (int it = 0; it < 64; it++) {
#pragma unroll
        for (int j = 0; j < 4; j++) {
            const int q = it * 4 + j;        // sub-block index, 0..255
            // prefetch next sub-block into the other buffer
            if (q + 1 < 256) {
                if ((j & 1) == 0) {
#pragma unroll
                    for (int j2 = 0; j2 < 16; j2++) bufB[j2] = wp[(q + 1) * 16 + j2];
                    ncB = ncp[q + 1];
                } else {
#pragma unroll
                    for (int j2 = 0; j2 < 16; j2++) bufA[j2] = wp[(q + 1) * 16 + j2];
                    ncA = ncp[q + 1];
                }
            }
#pragma unroll
            for (int t = 0; t < 4; t++) {
                const int s = j * 4 + t;        // step within 16-step ring
                const int e = it * 16 + s;      // global step

                float4 rr0, rr1, rr2, rr3;
                float ncv;
                if ((j & 1) == 0) {
                    rr0 = bufA[t * 4 + 0]; rr1 = bufA[t * 4 + 1];
                    rr2 = bufA[t * 4 + 2]; rr3 = bufA[t * 4 + 3];
                    ncv = (t == 0) ? ncA.x : (t == 1) ? ncA.y : (t == 2) ? ncA.z : ncA.w;
                } else {
                    rr0 = bufB[t * 4 + 0]; rr1 = bufB[t * 4 + 1];
                    rr2 = bufB[t * 4 + 2]; rr3 = bufB[t * 4 + 3];
                    ncv = (t == 0) ? ncB.x : (t == 1) ? ncB.y : (t == 2) ? ncB.z : ncB.w;
                }

                // zz[(s-k)&15] holds z_{e-k}. Four 4-FFMA chains; the z_e tap
                // (k=0) is applied last so the step-to-step critical edge is
                // a single FFMA + FADDs.
                float p3 = zz[(s - 15 + 32) & 15] * rr3.w;
                p3 = fmaf(zz[(s - 14 + 32) & 15], rr3.z, p3);
                p3 = fmaf(zz[(s - 13 + 32) & 15], rr3.y, p3);
                p3 = fmaf(zz[(s - 12 + 32) & 15], rr3.x, p3);

                float p2 = zz[(s - 11 + 32) & 15] * rr2.w;
                p2 = fmaf(zz[(s - 10 + 32) & 15], rr2.z, p2);
                p2 = fmaf(zz[(s -  9 + 32) & 15], rr2.y, p2);
                p2 = fmaf(zz[(s -  8 + 32) & 15], rr2.x, p2);

                float p1 = zz[(s -  7 + 32) & 15] * rr1.w;
                p1 = fmaf(zz[(s -  6 + 32) & 15], rr1.z, p1);
                p1 = fmaf(zz[(s -  5 + 32) & 15], rr1.y, p1);
                p1 = fmaf(zz[(s -  4 + 32) & 15], rr1.x, p1);

                float p0 = zz[(s -  3 + 32) & 15] * rr0.w;
                p0 = fmaf(zz[(s -  2 + 32) & 15], rr0.z, p0);
                p0 = fmaf(zz[(s -  1 + 32) & 15], rr0.y, p0);

                float zn = ((p3 + p2) + p1) + p0;
                zn = fmaf(zz[(s + 32) & 15], rr0.x, zn);   // k=0 tap last

                zz[(s + 1) & 15] = zn;

                if (e < len) num += ncv;
                if (e + 1 == len) {
                    den = ((float)C + lg2f_(zn)) * LN2;    // alpha[len] in nats
                }

                // exact power-of-2 renorm every 4 steps
                if (t == 3) {
                    int d = ((__float_as_int(zn) >> 23) & 255) - 127;
                    C += d;
                    float scale = __int_as_float((127 - d) << 23);
#pragma unroll
                    for (int k = 0; k < 16; k++) zz[k] *= scale;
                }
            }
        }
    }

    float res = den - num;
#pragma unroll
    for (int o = 16; o > 0; o >>= 1) res += __shfl_xor_sync(0xffffffffu, res, o);
    if (threadIdx.x == 0) atomicAdd(out, res);   // 2 blocks; fp-add commutative -> deterministic
}

// ---------------------------------------------------------------------------
extern "C" void kernel_launch(void* const* d_in, const int* in_sizes, int n_in,
                              void* d_out, int out_size)
{
    const float* tr   = (const float*)d_in[0];   // [B,S,L,T] f32
    const int*   tags = (const int*)  d_in[1];   // [B,S] i32
    const int*   lens = (const int*)  d_in[2];   // [B] i32
    float*       out  = (float*)d_out;           // scalar f32

    // 65536 (b,e) warps -> 8192 blocks of 256 threads
    semicrf_rowsum<<<8192, 256>>>(tr, tags, out);
    // 64 batch threads -> 2 blocks of 32 (one warp per block, each on its own SM)
    semicrf_scan<<<2, 32>>>(lens, out);
}

// round 2
// speedup vs baseline: 3.7338x; 3.7338x over previous
#include <cuda_runtime.h>

// Problem shape (fixed for this instance)
#define B_ 64
#define S_ 1024
#define L_ 16
#define T_ 32
#define NSEG 64            // S_ / L_

#define LOG2E 1.4426950408889634f
#define LN2   0.6931471805599453f

// Scratch (static __device__ arrays — allocation-free per harness rules)
__device__ __align__(16) float g_w [B_ * S_ * L_];     // w[b][e][k] = sum_t exp(tr[b,e,k,t])  (4 MB)
__device__ __align__(16) float g_nc[B_ * S_];          // nc[b][e]  = tr[b,e,0,tags[b,e]]
__device__ __align__(16) float g_A [B_ * NSEG * 256];  // per-segment 16x16 transition matrices (4 MB)
__device__             int   g_C [B_ * NSEG];          // per-segment power-of-2 scale exponents

__device__ __forceinline__ float ex2f_(float x) {
    float r; asm("ex2.approx.f32 %0, %1;" : "=f"(r) : "f"(x)); return r;
}
__device__ __forceinline__ float lg2f_(float x) {
    float r; asm("lg2.approx.f32 %0, %1;" : "=f"(r) : "f"(x)); return r;
}
__device__ __forceinline__ int clampd_(int d) {
    return d < -120 ? -120 : (d > 120 ? 120 : d);
}

// ---------------------------------------------------------------------------
// Kernel A (unchanged, ~roofline): one warp per (b,e) pair — computes
// w[k] = sum_t exp(tr[k,t]) over the [16,32] tile plus the numerator gather.
// ---------------------------------------------------------------------------
__global__ __launch_bounds__(256) void semicrf_rowsum(
    const float* __restrict__ tr,
    const int*   __restrict__ tags,
    float*       __restrict__ out)
{
    if (blockIdx.x == 0 && threadIdx.x == 0) out[0] = 0.0f;

    const int wid  = (blockIdx.x * 256 + threadIdx.x) >> 5;   // (b*S + e)
    const int lane = threadIdx.x & 31;
    const float4* base = reinterpret_cast<const float4*>(tr) + (size_t)wid * 128;
    const int sub = lane >> 3;

    float rs[4];
#pragma unroll
    for (int i = 0; i < 4; i++) {
        float4 v = base[i * 32 + lane];
        float s = ex2f_(v.x * LOG2E) + ex2f_(v.y * LOG2E)
                + ex2f_(v.z * LOG2E) + ex2f_(v.w * LOG2E);
        s += __shfl_xor_sync(0xffffffffu, s, 1);
        s += __shfl_xor_sync(0xffffffffu, s, 2);
        s += __shfl_xor_sync(0xffffffffu, s, 4);
        rs[i] = s;
    }
    if ((lane & 7) == 0) {
        float* wb = g_w + (size_t)wid * 16;
#pragma unroll
        for (int i = 0; i < 4; i++) wb[i * 4 + sub] = rs[i];
    }
    if (lane == 0) {
        int tag = tags[wid];
        g_nc[wid] = tr[(size_t)wid * 512 + tag];
    }
}

// ---------------------------------------------------------------------------
// Kernel BUILD: fold 16 companion matrices into one dense 16x16 per segment.
// One 16-lane half-warp per (b,seg); lane c owns matrix column c.
// Ring zz[16] holds the rows (reps of z in the v_start basis).
// ---------------------------------------------------------------------------
__global__ __launch_bounds__(256) void semicrf_build()
{
    __shared__ float sw[8][512];           // 2 units x 256 floats per warp
    const int warp = threadIdx.x >> 5;
    const int lane = threadIdx.x & 31;
    const int half = lane >> 4;
    const int hl   = lane & 15;
    const int unit = (blockIdx.x * 8 + warp) * 2 + half;   // 0..4095
    const int b    = unit >> 6;
    const int seg  = unit & 63;

    // stage this unit's 256 w values (16 steps x 16 taps, contiguous)
    {
        const float4* src = reinterpret_cast<const float4*>(
            g_w + ((size_t)b * S_ + seg * 16) * 16);
        float4* dst = reinterpret_cast<float4*>(&sw[warp][half * 256]);
#pragma unroll
        for (int i = 0; i < 4; i++) dst[i * 16 + hl] = src[i * 16 + hl];
    }
    __syncwarp();
    const float4* wv = reinterpret_cast<const float4*>(&sw[warp][half * 256]);

    // ring init = identity: zz[(16-c)&15] = 1 on lane c (static indices only)
    float zz[16];
#pragma unroll
    for (int k = 0; k < 16; k++) zz[k] = (k == ((16 - hl) & 15)) ? 1.0f : 0.0f;
    // note: (16-hl)&15 is runtime, but the comparison per compile-time k keeps
    // zz[] in registers (SEL), no dynamic indexing.

    int C = 0;
#pragma unroll
    for (int s = 0; s < 16; s++) {
        float4 rr0 = wv[s * 4 + 0], rr1 = wv[s * 4 + 1];
        float4 rr2 = wv[s * 4 + 2], rr3 = wv[s * 4 + 3];

        float p3 = zz[(s - 15 + 32) & 15] * rr3.w;
        p3 = fmaf(zz[(s - 14 + 32) & 15], rr3.z, p3);
        p3 = fmaf(zz[(s - 13 + 32) & 15], rr3.y, p3);
        p3 = fmaf(zz[(s - 12 + 32) & 15], rr3.x, p3);

        float p2 = zz[(s - 11 + 32) & 15] * rr2.w;
        p2 = fmaf(zz[(s - 10 + 32) & 15], rr2.z, p2);
        p2 = fmaf(zz[(s -  9 + 32) & 15], rr2.y, p2);
        p2 = fmaf(zz[(s -  8 + 32) & 15], rr2.x, p2);

        float p1 = zz[(s -  7 + 32) & 15] * rr1.w;
        p1 = fmaf(zz[(s -  6 + 32) & 15], rr1.z, p1);
        p1 = fmaf(zz[(s -  5 + 32) & 15], rr1.y, p1);
        p1 = fmaf(zz[(s -  4 + 32) & 15], rr1.x, p1);

        float p0 = zz[(s -  3 + 32) & 15] * rr0.w;
        p0 = fmaf(zz[(s -  2 + 32) & 15], rr0.z, p0);
        p0 = fmaf(zz[(s -  1 + 32) & 15], rr0.y, p0);

        float zn = ((p3 + p2) + p1) + p0;
        zn = fmaf(zz[s & 15], rr0.x, zn);
        zz[(s + 1) & 15] = zn;

        if ((s & 3) == 3) {   // exact power-of-2 renorm, target max ~ 2^60
            int ex = (__float_as_int(zn) >> 23) & 255;
            ex = max(ex, __shfl_xor_sync(0xffffffffu, ex, 1, 16));
            ex = max(ex, __shfl_xor_sync(0xffffffffu, ex, 2, 16));
            ex = max(ex, __shfl_xor_sync(0xffffffffu, ex, 4, 16));
            ex = max(ex, __shfl_xor_sync(0xffffffffu, ex, 8, 16));
            int d = clampd_(ex - (127 + 60));
            C += d;
            float sc = __int_as_float((127 - d) << 23);
#pragma unroll
            for (int k2 = 0; k2 < 16; k2++) zz[k2] *= sc;
        }
    }

    // store: row i of A (v_new[i] in v_old basis) = zz[(16-i)&15]; lane = col
    float* Adst = g_A + (size_t)unit * 256;
#pragma unroll
    for (int i = 0; i < 16; i++) Adst[i * 16 + hl] = zz[(16 - i) & 15];
    if (hl == 0) g_C[unit] = C;
}

// ---------------------------------------------------------------------------
// Kernel SCAN2: per batch, scan 64 segment matrices (matvec, lane i = row i,
// both 16-lane halves mirror each other), then replay the <=15-step tail.
// ---------------------------------------------------------------------------
__global__ __launch_bounds__(32) void semicrf_scan2(
    const int* __restrict__ lens,
    float*     __restrict__ out)
{
    const int b    = blockIdx.x;
    const int lane = threadIdx.x;
    const int hl   = lane & 15;
    const int len  = lens[b];

    // numerator: prefix sum of nc up to len
    float num = 0.0f;
    const float* ncb = g_nc + (size_t)b * S_;
    for (int e = lane; e < len; e += 32) num += ncb[e];
#pragma unroll
    for (int o = 16; o > 0; o >>= 1) num += __shfl_xor_sync(0xffffffffu, num, o);

    const int m = len >> 4;       // full segments
    const int r = len & 15;       // tail steps

    // v replicated across both halves; vf[k] = z_{16q - k} (scaled by 2^Cv)
    float vf[16];
#pragma unroll
    for (int k = 0; k < 16; k++) vf[k] = (k == 0) ? 1.0f : 0.0f;
    int Cv = 0;

    const float4* Ab = reinterpret_cast<const float4*>(g_A) + (size_t)b * NSEG * 64;
    const int*    Cb = g_C + b * NSEG;

    float4 c0, c1, c2, c3, n0, n1, n2, n3;
    int cc = 0, nc2 = 0;
    if (m > 0) {
        const float4* p = Ab + hl * 4;
        c0 = p[0]; c1 = p[1]; c2 = p[2]; c3 = p[3];
        cc = Cb[0];
    }
    for (int q = 0; q < m; q++) {
        if (q + 1 < m) {          // register double-buffer prefetch
            const float4* p = Ab + (q + 1) * 64 + hl * 4;
            n0 = p[0]; n1 = p[1]; n2 = p[2]; n3 = p[3];
            nc2 = Cb[q + 1];
        }
        // row dot: s = sum_k A[hl][k] * vf[k]
        float a0 = c0.x * vf[0];
        a0 = fmaf(c0.y, vf[1], a0); a0 = fmaf(c0.z, vf[2], a0); a0 = fmaf(c0.w, vf[3], a0);
        float a1 = c1.x * vf[4];
        a1 = fmaf(c1.y, vf[5], a1); a1 = fmaf(c1.z, vf[6], a1); a1 = fmaf(c1.w, vf[7], a1);
        float a2 = c2.x * vf[8];
        a2 = fmaf(c2.y, vf[9], a2); a2 = fmaf(c2.z, vf[10], a2); a2 = fmaf(c2.w, vf[11], a2);
        float a3 = c3.x * vf[12];
        a3 = fmaf(c3.y, vf[13], a3); a3 = fmaf(c3.z, vf[14], a3); a3 = fmaf(c3.w, vf[15], a3);
        float s = (a0 + a1) + (a2 + a3);

        // renorm to max component ~2^0 (both halves identical -> full-warp redux)
        int ex = (__float_as_int(s) >> 23) & 255;
        ex = __reduce_max_sync(0xffffffffu, ex);
        int d = clampd_(ex - 127);
        Cv += d + cc;
        s *= __int_as_float((127 - d) << 23);

        // broadcast new v to all lanes (width-16 -> both halves mirrored)
#pragma unroll
        for (int k = 0; k < 16; k++) vf[k] = __shfl_sync(0xffffffffu, s, k, 16);

        c0 = n0; c1 = n1; c2 = n2; c3 = n3; cc = nc2;
    }

    // tail replay: apply r raw steps from w (all lanes compute identically)
    float den = ((float)Cv + lg2f_(vf[0])) * LN2;     // covers r == 0
    if (r > 0) {
        float zz[16];
#pragma unroll
        for (int j = 0; j < 16; j++) zz[j] = vf[(16 - j) & 15];
        const float4* wb = reinterpret_cast<const float4*>(
            g_w + ((size_t)b * S_ + m * 16) * 16);
#pragma unroll
        for (int s2 = 0; s2 < 15; s2++) {
            if (s2 < r) {
                float4 rr0 = wb[s2 * 4 + 0], rr1 = wb[s2 * 4 + 1];
                float4 rr2 = wb[s2 * 4 + 2], rr3 = wb[s2 * 4 + 3];

                float p3 = zz[(s2 - 15 + 32) & 15] * rr3.w;
                p3 = fmaf(zz[(s2 - 14 + 32) & 15], rr3.z, p3);
                p3 = fmaf(zz[(s2 - 13 + 32) & 15], rr3.y, p3);
                p3 = fmaf(zz[(s2 - 12 + 32) & 15], rr3.x, p3);
                float p2 = zz[(s2 - 11 + 32) & 15] * rr2.w;
                p2 = fmaf(zz[(s2 - 10 + 32) & 15], rr2.z, p2);
                p2 = fmaf(zz[(s2 -  9 + 32) & 15], rr2.y, p2);
                p2 = fmaf(zz[(s2 -  8 + 32) & 15], rr2.x, p2);
                float p1 = zz[(s2 -  7 + 32) & 15] * rr1.w;
                p1 = fmaf(zz[(s2 -  6 + 32) & 15], rr1.z, p1);
                p1 = fmaf(zz[(s2 -  5 + 32) & 15], rr1.y, p1);
                p1 = fmaf(zz[(s2 -  4 + 32) & 15], rr1.x, p1);
                float p0 = zz[(s2 -  3 + 32) & 15] * rr0.w;
                p0 = fmaf(zz[(s2 -  2 + 32) & 15], rr0.z, p0);
                p0 = fmaf(zz[(s2 -  1 + 32) & 15], rr0.y, p0);

                float zn = ((p3 + p2) + p1) + p0;
                zn = fmaf(zz[s2 & 15], rr0.x, zn);

                if (s2 == r - 1) den = ((float)Cv + lg2f_(zn)) * LN2;

                zz[(s2 + 1) & 15] = zn;

                if ((s2 & 1) == 1) {   // uniform renorm (no shuffles needed)
                    int d2 = clampd_(((__float_as_int(zn) >> 23) & 255) - 127);
                    Cv += d2;
                    float sc = __int_as_float((127 - d2) << 23);
#pragma unroll
                    for (int k2 = 0; k2 < 16; k2++) zz[k2] *= sc;
                }
            }
        }
    }

    if (lane == 0) atomicAdd(out, den - num);
}

// ---------------------------------------------------------------------------
extern "C" void kernel_launch(void* const* d_in, const int* in_sizes, int n_in,
                              void* d_out, int out_size)
{
    const float* tr   = (const float*)d_in[0];   // [B,S,L,T] f32
    const int*   tags = (const int*)  d_in[1];   // [B,S] i32
    const int*   lens = (const int*)  d_in[2];   // [B] i32
    float*       out  = (float*)d_out;           // scalar f32

    semicrf_rowsum<<<8192, 256>>>(tr, tags, out);   // 65536 (b,e) warps
    semicrf_build<<<256, 256>>>();                  // 4096 segment matrices
    semicrf_scan2<<<64, 32>>>(lens, out);           // 64 batch warps
}

// round 3
// speedup vs baseline: 5.3719x; 1.4387x over previous
#include <cuda_runtime.h>

// Problem shape (fixed for this instance)
#define B_ 64
#define S_ 1024
#define L_ 16
#define T_ 32
#define NSEG 64            // S_ / L_
#define AROW 20            // padded row stride (floats) for the 16x16 matrices

#define LOG2E 1.4426950408889634f
#define LN2   0.6931471805599453f

// Scratch (static __device__ arrays — allocation-free per harness rules)
__device__ __align__(16) float g_w [B_ * S_ * L_];   // w[b][e][k] = sum_t exp(tr[b,e,k,t])  (4 MB)
__device__ __align__(16) float g_nc[B_ * S_];        // nc[b][e]  = tr[b,e,0,tags[b,e]]

// Dynamic smem layout for the fold kernel (floats):
//   sA   [NSEG * AROW*16]  = 64*320      matrices (row stride AROW)
//   sTail[256]                           raw w rows for the tail replay
//   sNum [16]                            per-warp numerator partials
//   sC   [64] (int)                      per-segment scale exponents
#define FOLD_SMEM_FLOATS (NSEG * AROW * 16 + 256 + 16 + 64)
#define FOLD_SMEM_BYTES  (FOLD_SMEM_FLOATS * 4)

__device__ __forceinline__ float ex2f_(float x) {
    float r; asm("ex2.approx.f32 %0, %1;" : "=f"(r) : "f"(x)); return r;
}
__device__ __forceinline__ float lg2f_(float x) {
    float r; asm("lg2.approx.f32 %0, %1;" : "=f"(r) : "f"(x)); return r;
}
__device__ __forceinline__ int clampd_(int d) {
    return d < -120 ? -120 : (d > 120 ? 120 : d);
}

// ---------------------------------------------------------------------------
// Kernel A: one warp per (b,e) pair — w[k] = sum_t exp(tr[k,t]) over the
// [16,32] tile plus the numerator gather. Streaming loads (__ldcs): tr is
// read exactly once.
// ---------------------------------------------------------------------------
__global__ __launch_bounds__(256) void semicrf_rowsum(
    const float* __restrict__ tr,
    const int*   __restrict__ tags,
    float*       __restrict__ out)
{
    if (blockIdx.x == 0 && threadIdx.x == 0) out[0] = 0.0f;

    const int wid  = (blockIdx.x * 256 + threadIdx.x) >> 5;   // (b*S + e)
    const int lane = threadIdx.x & 31;
    const float4* base = reinterpret_cast<const float4*>(tr) + (size_t)wid * 128;
    const int sub = lane >> 3;

    float rs[4];
#pragma unroll
    for (int i = 0; i < 4; i++) {
        float4 v = __ldcs(&base[i * 32 + lane]);
        float s = ex2f_(v.x * LOG2E) + ex2f_(v.y * LOG2E)
                + ex2f_(v.z * LOG2E) + ex2f_(v.w * LOG2E);
        s += __shfl_xor_sync(0xffffffffu, s, 1);
        s += __shfl_xor_sync(0xffffffffu, s, 2);
        s += __shfl_xor_sync(0xffffffffu, s, 4);
        rs[i] = s;
    }
    if ((lane & 7) == 0) {
        float* wb = g_w + (size_t)wid * 16;
#pragma unroll
        for (int i = 0; i < 4; i++) wb[i * 4 + sub] = rs[i];
    }
    if (lane == 0) {
        int tag = tags[wid];
        g_nc[wid] = tr[(size_t)wid * 512 + tag];
    }
}

// ---------------------------------------------------------------------------
// Kernel FOLD: one block per batch. Phase 1 (all 16 warps): build the 64
// per-segment 16x16 matrices into SMEM (each half-warp builds 2, staging w
// in-place into the matrix slot), stage the tail w rows, partial-sum the
// numerator. Phase 2 (warp 0): serial scan of 64 matvecs from SMEM + tail
// replay.
// ---------------------------------------------------------------------------
__global__ __launch_bounds__(512) void semicrf_fold(
    const int* __restrict__ lens,
    float*     __restrict__ out)
{
    extern __shared__ float smem[];
    float* sA    = smem;                        // NSEG * AROW*16
    float* sTail = smem + NSEG * AROW * 16;     // 256
    float* sNum  = sTail + 256;                 // 16
    int*   sC    = (int*)(sNum + 16);           // 64

    const int b    = blockIdx.x;
    const int tid  = threadIdx.x;
    const int warp = tid >> 5;
    const int lane = tid & 31;
    const int half = lane >> 4;
    const int hl   = lane & 15;
    const int unit = warp * 2 + half;           // 0..31

    const int len = lens[b];
    const int m   = len >> 4;
    const int r   = len & 15;

    // ---- numerator partials (all threads) ----
    {
        float np = 0.0f;
        const float* ncb = g_nc + (size_t)b * S_;
        for (int e = tid; e < len; e += 512) np += ncb[e];
#pragma unroll
        for (int o = 16; o > 0; o >>= 1) np += __shfl_xor_sync(0xffffffffu, np, o);
        if (lane == 0) sNum[warp] = np;
    }

    // ---- tail w staging (warp 1) ----
    if (warp == 1 && m < NSEG) {
        const float4* swp = reinterpret_cast<const float4*>(
            g_w + ((size_t)b * S_ + m * 16) * 16);
        float4* st = reinterpret_cast<float4*>(sTail);
        st[lane]      = swp[lane];
        st[lane + 32] = swp[lane + 32];
    }

    // ---- build 2 segment matrices per half-warp ----
#pragma unroll
    for (int rep = 0; rep < 2; rep++) {
        const int seg = unit + rep * 32;
        float* slot = sA + seg * (AROW * 16);

        // stage this segment's 256 w values in-place into the slot
        {
            const float4* src = reinterpret_cast<const float4*>(
                g_w + ((size_t)b * S_ + seg * 16) * 16);
            float4* dst = reinterpret_cast<float4*>(slot);
#pragma unroll
            for (int i = 0; i < 4; i++) dst[i * 16 + hl] = src[i * 16 + hl];
        }
        __syncwarp();
        const float4* wv = reinterpret_cast<const float4*>(slot);

        // ring init = identity column hl
        float zz[16];
#pragma unroll
        for (int k = 0; k < 16; k++) zz[k] = (k == ((16 - hl) & 15)) ? 1.0f : 0.0f;

        int C = 0;
#pragma unroll
        for (int s = 0; s < 16; s++) {
            float4 rr0 = wv[s * 4 + 0], rr1 = wv[s * 4 + 1];
            float4 rr2 = wv[s * 4 + 2], rr3 = wv[s * 4 + 3];

            float p3 = zz[(s - 15 + 32) & 15] * rr3.w;
            p3 = fmaf(zz[(s - 14 + 32) & 15], rr3.z, p3);
            p3 = fmaf(zz[(s - 13 + 32) & 15], rr3.y, p3);
            p3 = fmaf(zz[(s - 12 + 32) & 15], rr3.x, p3);

            float p2 = zz[(s - 11 + 32) & 15] * rr2.w;
            p2 = fmaf(zz[(s - 10 + 32) & 15], rr2.z, p2);
            p2 = fmaf(zz[(s -  9 + 32) & 15], rr2.y, p2);
            p2 = fmaf(zz[(s -  8 + 32) & 15], rr2.x, p2);

            float p1 = zz[(s -  7 + 32) & 15] * rr1.w;
            p1 = fmaf(zz[(s -  6 + 32) & 15], rr1.z, p1);
            p1 = fmaf(zz[(s -  5 + 32) & 15], rr1.y, p1);
            p1 = fmaf(zz[(s -  4 + 32) & 15], rr1.x, p1);

            float p0 = zz[(s -  3 + 32) & 15] * rr0.w;
            p0 = fmaf(zz[(s -  2 + 32) & 15], rr0.z, p0);
            p0 = fmaf(zz[(s -  1 + 32) & 15], rr0.y, p0);

            float zn = ((p3 + p2) + p1) + p0;
            zn = fmaf(zz[s & 15], rr0.x, zn);
            zz[(s + 1) & 15] = zn;

            if ((s & 3) == 3) {   // exact power-of-2 renorm, target max ~ 2^60
                int ex = (__float_as_int(zn) >> 23) & 255;
                ex = max(ex, __shfl_xor_sync(0xffffffffu, ex, 1, 16));
                ex = max(ex, __shfl_xor_sync(0xffffffffu, ex, 2, 16));
                ex = max(ex, __shfl_xor_sync(0xffffffffu, ex, 4, 16));
                ex = max(ex, __shfl_xor_sync(0xffffffffu, ex, 8, 16));
                int d = clampd_(ex - (127 + 60));
                C += d;
                float sc = __int_as_float((127 - d) << 23);
#pragma unroll
                for (int k2 = 0; k2 < 16; k2++) zz[k2] *= sc;
            }
        }

        __syncwarp();   // all w reads done before overwriting the slot
        // row i of A = zz[(16-i)&15]; lane hl = column
#pragma unroll
        for (int i = 0; i < 16; i++) slot[i * AROW + hl] = zz[(16 - i) & 15];
        if (hl == 0) sC[seg] = C;
    }

    __syncthreads();

    // ---- scan (warp 0 only) ----
    if (warp == 0) {
        // vf replicated on all lanes; vf[k] = z_{16q-k} scaled by 2^Cv
        float vf[16];
#pragma unroll
        for (int k = 0; k < 16; k++) vf[k] = (k == 0) ? 1.0f : 0.0f;
        int Cv = 0;

        float4 c0, c1, c2, c3, n0, n1, n2, n3;
        int cc = 0, cn = 0;
        if (m > 0) {
            const float4* rp = reinterpret_cast<const float4*>(sA + hl * AROW);
            c0 = rp[0]; c1 = rp[1]; c2 = rp[2]; c3 = rp[3];
            cc = sC[0];
        }
        for (int q = 0; q < m; q++) {
            if (q + 1 < m) {
                const float4* rp = reinterpret_cast<const float4*>(
                    sA + (q + 1) * (AROW * 16) + hl * AROW);
                n0 = rp[0]; n1 = rp[1]; n2 = rp[2]; n3 = rp[3];
                cn = sC[q + 1];
            }
            float a0 = c0.x * vf[0];
            a0 = fmaf(c0.y, vf[1], a0); a0 = fmaf(c0.z, vf[2], a0); a0 = fmaf(c0.w, vf[3], a0);
            float a1 = c1.x * vf[4];
            a1 = fmaf(c1.y, vf[5], a1); a1 = fmaf(c1.z, vf[6], a1); a1 = fmaf(c1.w, vf[7], a1);
            float a2 = c2.x * vf[8];
            a2 = fmaf(c2.y, vf[9], a2); a2 = fmaf(c2.z, vf[10], a2); a2 = fmaf(c2.w, vf[11], a2);
            float a3 = c3.x * vf[12];
            a3 = fmaf(c3.y, vf[13], a3); a3 = fmaf(c3.z, vf[14], a3); a3 = fmaf(c3.w, vf[15], a3);
            float s = (a0 + a1) + (a2 + a3);

            // broadcast rows -> full vector on every lane (width 16, halves mirror)
#pragma unroll
            for (int k = 0; k < 16; k++) vf[k] = __shfl_sync(0xffffffffu, s, k, 16);

            // local renorm: max exponent over the (replicated) vector
            int ex = 0;
#pragma unroll
            for (int k = 0; k < 16; k++)
                ex = max(ex, (__float_as_int(vf[k]) >> 23) & 255);
            int d = clampd_(ex - 127);
            Cv += d + cc;
            float sc = __int_as_float((127 - d) << 23);
#pragma unroll
            for (int k = 0; k < 16; k++) vf[k] *= sc;

            c0 = n0; c1 = n1; c2 = n2; c3 = n3; cc = cn;
        }

        float den = ((float)Cv + lg2f_(vf[0])) * LN2;   // covers r == 0
        if (r > 0) {
            float zz[16];
#pragma unroll
            for (int j = 0; j < 16; j++) zz[j] = vf[(16 - j) & 15];
            const float4* wb = reinterpret_cast<const float4*>(sTail);
#pragma unroll
            for (int s2 = 0; s2 < 15; s2++) {
                if (s2 < r) {
                    float4 rr0 = wb[s2 * 4 + 0], rr1 = wb[s2 * 4 + 1];
                    float4 rr2 = wb[s2 * 4 + 2], rr3 = wb[s2 * 4 + 3];

                    float p3 = zz[(s2 - 15 + 32) & 15] * rr3.w;
                    p3 = fmaf(zz[(s2 - 14 + 32) & 15], rr3.z, p3);
                    p3 = fmaf(zz[(s2 - 13 + 32) & 15], rr3.y, p3);
                    p3 = fmaf(zz[(s2 - 12 + 32) & 15], rr3.x, p3);
                    float p2 = zz[(s2 - 11 + 32) & 15] * rr2.w;
                    p2 = fmaf(zz[(s2 - 10 + 32) & 15], rr2.z, p2);
                    p2 = fmaf(zz[(s2 -  9 + 32) & 15], rr2.y, p2);
                    p2 = fmaf(zz[(s2 -  8 + 32) & 15], rr2.x, p2);
                    float p1 = zz[(s2 -  7 + 32) & 15] * rr1.w;
                    p1 = fmaf(zz[(s2 -  6 + 32) & 15], rr1.z, p1);
                    p1 = fmaf(zz[(s2 -  5 + 32) & 15], rr1.y, p1);
                    p1 = fmaf(zz[(s2 -  4 + 32) & 15], rr1.x, p1);
                    float p0 = zz[(s2 -  3 + 32) & 15] * rr0.w;
                    p0 = fmaf(zz[(s2 -  2 + 32) & 15], rr0.z, p0);
                    p0 = fmaf(zz[(s2 -  1 + 32) & 15], rr0.y, p0);

                    float zn = ((p3 + p2) + p1) + p0;
                    zn = fmaf(zz[s2 & 15], rr0.x, zn);

                    if (s2 == r - 1) den = ((float)Cv + lg2f_(zn)) * LN2;

                    zz[(s2 + 1) & 15] = zn;

                    if ((s2 & 1) == 1) {
                        int d2 = clampd_(((__float_as_int(zn) >> 23) & 255) - 127);
                        Cv += d2;
                        float sc2 = __int_as_float((127 - d2) << 23);
#pragma unroll
                        for (int k2 = 0; k2 < 16; k2++) zz[k2] *= sc2;
                    }
                }
            }
        }

        // numerator total from per-warp partials
        float nt = (lane < 16) ? sNum[lane] : 0.0f;
#pragma unroll
        for (int o = 16; o > 0; o >>= 1) nt += __shfl_xor_sync(0xffffffffu, nt, o);

        if (lane == 0) atomicAdd(out, den - nt);
    }
}

// ---------------------------------------------------------------------------
extern "C" void kernel_launch(void* const* d_in, const int* in_sizes, int n_in,
                              void* d_out, int out_size)
{
    const float* tr   = (const float*)d_in[0];   // [B,S,L,T] f32
    const int*   tags = (const int*)  d_in[1];   // [B,S] i32
    const int*   lens = (const int*)  d_in[2];   // [B] i32
    float*       out  = (float*)d_out;           // scalar f32

    cudaFuncSetAttribute(semicrf_fold,
                         cudaFuncAttributeMaxDynamicSharedMemorySize,
                         FOLD_SMEM_BYTES);

    semicrf_rowsum<<<8192, 256>>>(tr, tags, out);           // 65536 (b,e) warps
    semicrf_fold<<<64, 512, FOLD_SMEM_BYTES>>>(lens, out);  // one block per batch
}

// round 4
// speedup vs baseline: 5.6376x; 1.0495x over previous
#include <cuda_runtime.h>

// Problem shape (fixed for this instance)
#define B_ 64
#define S_ 1024
#define L_ 16
#define T_ 32
#define NSEG 64            // S_ / L_
#define AROW 20            // padded row stride (floats) for the 16x16 matrices
#define MSLOT (AROW * 16)  // 320 floats per matrix slot

#define LOG2E 1.4426950408889634f
#define LN2   0.6931471805599453f

// Scratch (static __device__ arrays — allocation-free per harness rules)
__device__ __align__(16) float g_w [B_ * S_ * L_];   // w[b][e][k] = sum_t exp(tr[b,e,k,t])
__device__ __align__(16) float g_nc[B_ * S_];        // nc[b][e]  = tr[b,e,0,tags[b,e]]

// Dynamic smem layout (floats):
//   sA0  [64 * MSLOT]   level-0 16-step matrices
//   sP1  [32 * MSLOT]   level-1 (32-step)
//   sP2  [16 * MSLOT]   level-2 (64-step)
//   sP3  [ 8 * MSLOT]   level-3 (128-step chunks)
//   sTail[256]          raw w rows for the <16-step tail
//   sNum [16]           per-warp numerator partials
//   sC0[64] sC1[32] sC2[16] sC3[8]  (ints) scale exponents
#define FOLD_SMEM_FLOATS ((64 + 32 + 16 + 8) * MSLOT + 256 + 16 + 120)
#define FOLD_SMEM_BYTES  (FOLD_SMEM_FLOATS * 4)

__device__ __forceinline__ float ex2f_(float x) {
    float r; asm("ex2.approx.f32 %0, %1;" : "=f"(r) : "f"(x)); return r;
}
__device__ __forceinline__ float lg2f_(float x) {
    float r; asm("lg2.approx.f32 %0, %1;" : "=f"(r) : "f"(x)); return r;
}
__device__ __forceinline__ int clampd_(int d) {
    return d < -120 ? -120 : (d > 120 ? 120 : d);
}
__device__ __forceinline__ int expo_(float x) {
    return (__float_as_int(x) >> 23) & 255;
}

// ---------------------------------------------------------------------------
// Kernel A: one warp per (b,e) pair — w[k] = sum_t exp(tr[k,t]) plus the
// numerator gather. Streaming loads: tr is read exactly once.
// ---------------------------------------------------------------------------
__global__ __launch_bounds__(256) void semicrf_rowsum(
    const float* __restrict__ tr,
    const int*   __restrict__ tags,
    float*       __restrict__ out)
{
    if (blockIdx.x == 0 && threadIdx.x == 0) out[0] = 0.0f;

    const int wid  = (blockIdx.x * 256 + threadIdx.x) >> 5;   // (b*S + e)
    const int lane = threadIdx.x & 31;
    const float4* base = reinterpret_cast<const float4*>(tr) + (size_t)wid * 128;
    const int sub = lane >> 3;

    float rs[4];
#pragma unroll
    for (int i = 0; i < 4; i++) {
        float4 v = __ldcs(&base[i * 32 + lane]);
        float s = ex2f_(v.x * LOG2E) + ex2f_(v.y * LOG2E)
                + ex2f_(v.z * LOG2E) + ex2f_(v.w * LOG2E);
        s += __shfl_xor_sync(0xffffffffu, s, 1);
        s += __shfl_xor_sync(0xffffffffu, s, 2);
        s += __shfl_xor_sync(0xffffffffu, s, 4);
        rs[i] = s;
    }
    if ((lane & 7) == 0) {
        float* wb = g_w + (size_t)wid * 16;
#pragma unroll
        for (int i = 0; i < 4; i++) wb[i * 4 + sub] = rs[i];
    }
    if (lane == 0) {
        int tag = tags[wid];
        g_nc[wid] = tr[(size_t)wid * 512 + tag];
    }
}

// ---------------------------------------------------------------------------
// 16x16 matrix product D = Am * Bm, one column (hl) per lane of a half-warp.
// Matrices row-major with row stride AROW; result max-normalized to ~2^0,
// exponent accumulated into *Cdst.
// ---------------------------------------------------------------------------
__device__ __forceinline__ void matmul16(
    const float* __restrict__ Am, const float* __restrict__ Bm,
    float* __restrict__ Dst, int Ca, int Cb, int* __restrict__ Cdst, int hl)
{
    float bc[16];
#pragma unroll
    for (int k = 0; k < 16; k++) bc[k] = Bm[k * AROW + hl];

    float r[16];
#pragma unroll
    for (int i = 0; i < 16; i++) {
        const float4* ar = reinterpret_cast<const float4*>(Am + i * AROW);
        float4 a0 = ar[0], a1 = ar[1], a2 = ar[2], a3 = ar[3];
        float s0 = a0.x * bc[0];
        s0 = fmaf(a0.y, bc[1], s0); s0 = fmaf(a0.z, bc[2], s0); s0 = fmaf(a0.w, bc[3], s0);
        float s1 = a1.x * bc[4];
        s1 = fmaf(a1.y, bc[5], s1); s1 = fmaf(a1.z, bc[6], s1); s1 = fmaf(a1.w, bc[7], s1);
        float s2 = a2.x * bc[8];
        s2 = fmaf(a2.y, bc[9], s2); s2 = fmaf(a2.z, bc[10], s2); s2 = fmaf(a2.w, bc[11], s2);
        float s3 = a3.x * bc[12];
        s3 = fmaf(a3.y, bc[13], s3); s3 = fmaf(a3.z, bc[14], s3); s3 = fmaf(a3.w, bc[15], s3);
        r[i] = (s0 + s1) + (s2 + s3);
    }

    int ex = 0;
#pragma unroll
    for (int i = 0; i < 16; i++) ex = max(ex, expo_(r[i]));
    ex = max(ex, __shfl_xor_sync(0xffffffffu, ex, 1, 16));
    ex = max(ex, __shfl_xor_sync(0xffffffffu, ex, 2, 16));
    ex = max(ex, __shfl_xor_sync(0xffffffffu, ex, 4, 16));
    ex = max(ex, __shfl_xor_sync(0xffffffffu, ex, 8, 16));
    int d = clampd_(ex - 127);
    float sc = __int_as_float((127 - d) << 23);
#pragma unroll
    for (int i = 0; i < 16; i++) Dst[i * AROW + hl] = r[i] * sc;
    if (hl == 0) *Cdst = Ca + Cb + d;
}

// One serial matvec step: vf <- normalize(M * vf); M row hl per lane, vf
// replicated on all 32 lanes (halves mirror via width-16 shfl).
__device__ __forceinline__ void matvec16(
    const float* __restrict__ M, int Cm, float* vf, int& Cv, int hl)
{
    const float4* rp = reinterpret_cast<const float4*>(M + hl * AROW);
    float4 c0 = rp[0], c1 = rp[1], c2 = rp[2], c3 = rp[3];
    float a0 = c0.x * vf[0];
    a0 = fmaf(c0.y, vf[1], a0); a0 = fmaf(c0.z, vf[2], a0); a0 = fmaf(c0.w, vf[3], a0);
    float a1 = c1.x * vf[4];
    a1 = fmaf(c1.y, vf[5], a1); a1 = fmaf(c1.z, vf[6], a1); a1 = fmaf(c1.w, vf[7], a1);
    float a2 = c2.x * vf[8];
    a2 = fmaf(c2.y, vf[9], a2); a2 = fmaf(c2.z, vf[10], a2); a2 = fmaf(c2.w, vf[11], a2);
    float a3 = c3.x * vf[12];
    a3 = fmaf(c3.y, vf[13], a3); a3 = fmaf(c3.z, vf[14], a3); a3 = fmaf(c3.w, vf[15], a3);
    float s = (a0 + a1) + (a2 + a3);
#pragma unroll
    for (int k = 0; k < 16; k++) vf[k] = __shfl_sync(0xffffffffu, s, k, 16);
    int ex = 0;
#pragma unroll
    for (int k = 0; k < 16; k++) ex = max(ex, expo_(vf[k]));
    int d = clampd_(ex - 127);
    Cv += d + Cm;
    float sc = __int_as_float((127 - d) << 23);
#pragma unroll
    for (int k = 0; k < 16; k++) vf[k] *= sc;
}

// ---------------------------------------------------------------------------
// Kernel FOLD: one block (512 thr) per batch.
//   P1: build 64 level-0 matrices (max-normalized) into SMEM.
//   P2: 3 levels of pairwise products -> 8 chunk (128-step) matrices.
//   P3 (warp 0): <=8 chunk matvecs + <=7 segment matvecs + <=15 raw steps.
// ---------------------------------------------------------------------------
__global__ __launch_bounds__(512) void semicrf_fold(
    const int* __restrict__ lens,
    float*     __restrict__ out)
{
    extern __shared__ float smem[];
    float* sA0   = smem;
    float* sP1   = sA0 + 64 * MSLOT;
    float* sP2   = sP1 + 32 * MSLOT;
    float* sP3   = sP2 + 16 * MSLOT;
    float* sTail = sP3 + 8 * MSLOT;     // 256
    float* sNum  = sTail + 256;         // 16
    int*   sC0   = (int*)(sNum + 16);   // 64
    int*   sC1   = sC0 + 64;            // 32
    int*   sC2   = sC1 + 32;            // 16
    int*   sC3   = sC2 + 16;            // 8

    const int b    = blockIdx.x;
    const int tid  = threadIdx.x;
    const int warp = tid >> 5;
    const int lane = tid & 31;
    const int half = lane >> 4;
    const int hl   = lane & 15;
    const int unit = warp * 2 + half;   // 0..31

    const int len = lens[b];
    const int m   = len >> 4;           // full 16-step segments
    const int rem = len & 15;           // raw tail steps

    // ---- numerator partials (all threads) ----
    {
        float np = 0.0f;
        const float* ncb = g_nc + (size_t)b * S_;
        for (int e = tid; e < len; e += 512) np += ncb[e];
#pragma unroll
        for (int o = 16; o > 0; o >>= 1) np += __shfl_xor_sync(0xffffffffu, np, o);
        if (lane == 0) sNum[warp] = np;
    }

    // ---- tail w staging (warp 15) ----
    if (warp == 15 && m < NSEG) {
        const float4* swp = reinterpret_cast<const float4*>(
            g_w + ((size_t)b * S_ + m * 16) * 16);
        float4* st = reinterpret_cast<float4*>(sTail);
        st[lane]      = swp[lane];
        st[lane + 32] = swp[lane + 32];
    }

    // ---- P1: build 2 level-0 matrices per half-warp ----
#pragma unroll
    for (int rep = 0; rep < 2; rep++) {
        const int seg = unit + rep * 32;
        float* slot = sA0 + seg * MSLOT;

        {   // stage this segment's 256 w values in-place into the slot
            const float4* src = reinterpret_cast<const float4*>(
                g_w + ((size_t)b * S_ + seg * 16) * 16);
            float4* dst = reinterpret_cast<float4*>(slot);
#pragma unroll
            for (int i = 0; i < 4; i++) dst[i * 16 + hl] = src[i * 16 + hl];
        }
        __syncwarp();
        const float4* wv = reinterpret_cast<const float4*>(slot);

        float zz[16];
#pragma unroll
        for (int k = 0; k < 16; k++) zz[k] = (k == ((16 - hl) & 15)) ? 1.0f : 0.0f;

        int C = 0;
#pragma unroll
        for (int s = 0; s < 16; s++) {
            float4 rr0 = wv[s * 4 + 0], rr1 = wv[s * 4 + 1];
            float4 rr2 = wv[s * 4 + 2], rr3 = wv[s * 4 + 3];

            float p3 = zz[(s - 15 + 32) & 15] * rr3.w;
            p3 = fmaf(zz[(s - 14 + 32) & 15], rr3.z, p3);
            p3 = fmaf(zz[(s - 13 + 32) & 15], rr3.y, p3);
            p3 = fmaf(zz[(s - 12 + 32) & 15], rr3.x, p3);
            float p2 = zz[(s - 11 + 32) & 15] * rr2.w;
            p2 = fmaf(zz[(s - 10 + 32) & 15], rr2.z, p2);
            p2 = fmaf(zz[(s -  9 + 32) & 15], rr2.y, p2);
            p2 = fmaf(zz[(s -  8 + 32) & 15], rr2.x, p2);
            float p1 = zz[(s -  7 + 32) & 15] * rr1.w;
            p1 = fmaf(zz[(s -  6 + 32) & 15], rr1.z, p1);
            p1 = fmaf(zz[(s -  5 + 32) & 15], rr1.y, p1);
            p1 = fmaf(zz[(s -  4 + 32) & 15], rr1.x, p1);
            float p0 = zz[(s -  3 + 32) & 15] * rr0.w;
            p0 = fmaf(zz[(s -  2 + 32) & 15], rr0.z, p0);
            p0 = fmaf(zz[(s -  1 + 32) & 15], rr0.y, p0);

            float zn = ((p3 + p2) + p1) + p0;
            zn = fmaf(zz[s & 15], rr0.x, zn);
            zz[(s + 1) & 15] = zn;

            if ((s & 3) == 3 && s != 15) {   // interim renorm: target max ~2^0
                int ex = expo_(zn);
                ex = max(ex, __shfl_xor_sync(0xffffffffu, ex, 1, 16));
                ex = max(ex, __shfl_xor_sync(0xffffffffu, ex, 2, 16));
                ex = max(ex, __shfl_xor_sync(0xffffffffu, ex, 4, 16));
                ex = max(ex, __shfl_xor_sync(0xffffffffu, ex, 8, 16));
                int d = clampd_(ex - 127);
                C += d;
                float sc = __int_as_float((127 - d) << 23);
#pragma unroll
                for (int k2 = 0; k2 < 16; k2++) zz[k2] *= sc;
            }
        }

        // final renorm: true matrix max -> ~2^0
        {
            int ex = 0;
#pragma unroll
            for (int k = 0; k < 16; k++) ex = max(ex, expo_(zz[k]));
            ex = max(ex, __shfl_xor_sync(0xffffffffu, ex, 1, 16));
            ex = max(ex, __shfl_xor_sync(0xffffffffu, ex, 2, 16));
            ex = max(ex, __shfl_xor_sync(0xffffffffu, ex, 4, 16));
            ex = max(ex, __shfl_xor_sync(0xffffffffu, ex, 8, 16));
            int d = clampd_(ex - 127);
            C += d;
            float sc = __int_as_float((127 - d) << 23);
#pragma unroll
            for (int k = 0; k < 16; k++) zz[k] *= sc;
        }

        __syncwarp();   // all w reads complete before overwriting the slot
#pragma unroll
        for (int i = 0; i < 16; i++) slot[i * AROW + hl] = zz[(16 - i) & 15];
        if (hl == 0) sC0[seg] = C;
    }
    __syncthreads();

    // ---- P2: pairwise products, 3 levels ----
    {   // level 1: 32 products (all half-warps)
        int u = unit;
        matmul16(sA0 + (2 * u + 1) * MSLOT, sA0 + (2 * u) * MSLOT,
                 sP1 + u * MSLOT, sC0[2 * u + 1], sC0[2 * u], &sC1[u], hl);
    }
    __syncthreads();
    if (warp < 8) {   // level 2: 16 products
        int u = unit;
        matmul16(sP1 + (2 * u + 1) * MSLOT, sP1 + (2 * u) * MSLOT,
                 sP2 + u * MSLOT, sC1[2 * u + 1], sC1[2 * u], &sC2[u], hl);
    }
    __syncthreads();
    if (warp < 4) {   // level 3: 8 products (128-step chunks)
        int u = unit;
        matmul16(sP2 + (2 * u + 1) * MSLOT, sP2 + (2 * u) * MSLOT,
                 sP3 + u * MSLOT, sC2[2 * u + 1], sC2[2 * u], &sC3[u], hl);
    }
    __syncthreads();

    // ---- P3: serial scan (warp 0) ----
    if (warp == 0) {
        float vf[16];
#pragma unroll
        for (int k = 0; k < 16; k++) vf[k] = (k == 0) ? 1.0f : 0.0f;
        int Cv = 0;

        const int qc   = len >> 7;        // full 128-step chunks (<=8)
        const int tseg = m & 7;           // remaining 16-step segments (<=7)

        for (int q = 0; q < qc; q++)
            matvec16(sP3 + q * MSLOT, sC3[q], vf, Cv, hl);
        for (int t = 0; t < tseg; t++)
            matvec16(sA0 + (qc * 8 + t) * MSLOT, sC0[qc * 8 + t], vf, Cv, hl);

        float den = ((float)Cv + lg2f_(vf[0])) * LN2;   // covers rem == 0
        if (rem > 0) {
            float zz[16];
#pragma unroll
            for (int j = 0; j < 16; j++) zz[j] = vf[(16 - j) & 15];
            const float4* wb = reinterpret_cast<const float4*>(sTail);
#pragma unroll
            for (int s2 = 0; s2 < 15; s2++) {
                if (s2 < rem) {
                    float4 rr0 = wb[s2 * 4 + 0], rr1 = wb[s2 * 4 + 1];
                    float4 rr2 = wb[s2 * 4 + 2], rr3 = wb[s2 * 4 + 3];

                    float p3 = zz[(s2 - 15 + 32) & 15] * rr3.w;
                    p3 = fmaf(zz[(s2 - 14 + 32) & 15], rr3.z, p3);
                    p3 = fmaf(zz[(s2 - 13 + 32) & 15], rr3.y, p3);
                    p3 = fmaf(zz[(s2 - 12 + 32) & 15], rr3.x, p3);
                    float p2 = zz[(s2 - 11 + 32) & 15] * rr2.w;
                    p2 = fmaf(zz[(s2 - 10 + 32) & 15], rr2.z, p2);
                    p2 = fmaf(zz[(s2 -  9 + 32) & 15], rr2.y, p2);
                    p2 = fmaf(zz[(s2 -  8 + 32) & 15], rr2.x, p2);
                    float p1 = zz[(s2 -  7 + 32) & 15] * rr1.w;
                    p1 = fmaf(zz[(s2 -  6 + 32) & 15], rr1.z, p1);
                    p1 = fmaf(zz[(s2 -  5 + 32) & 15], rr1.y, p1);
                    p1 = fmaf(zz[(s2 -  4 + 32) & 15], rr1.x, p1);
                    float p0 = zz[(s2 -  3 + 32) & 15] * rr0.w;
                    p0 = fmaf(zz[(s2 -  2 + 32) & 15], rr0.z, p0);
                    p0 = fmaf(zz[(s2 -  1 + 32) & 15], rr0.y, p0);

                    float zn = ((p3 + p2) + p1) + p0;
                    zn = fmaf(zz[s2 & 15], rr0.x, zn);

                    if (s2 == rem - 1) den = ((float)Cv + lg2f_(zn)) * LN2;

                    zz[(s2 + 1) & 15] = zn;

                    if ((s2 & 1) == 1) {   // uniform renorm (all lanes identical)
                        int d2 = clampd_(expo_(zn) - 127);
                        Cv += d2;
                        float sc2 = __int_as_float((127 - d2) << 23);
#pragma unroll
                        for (int k2 = 0; k2 < 16; k2++) zz[k2] *= sc2;
                    }
                }
            }
        }

        float nt = (lane < 16) ? sNum[lane] : 0.0f;
#pragma unroll
        for (int o = 16; o > 0; o >>= 1) nt += __shfl_xor_sync(0xffffffffu, nt, o);

        if (lane == 0) atomicAdd(out, den - nt);
    }
}

// ---------------------------------------------------------------------------
extern "C" void kernel_launch(void* const* d_in, const int* in_sizes, int n_in,
                              void* d_out, int out_size)
{
    const float* tr   = (const float*)d_in[0];   // [B,S,L,T] f32
    const int*   tags = (const int*)  d_in[1];   // [B,S] i32
    const int*   lens = (const int*)  d_in[2];   // [B] i32
    float*       out  = (float*)d_out;           // scalar f32

    cudaFuncSetAttribute(semicrf_fold,
                         cudaFuncAttributeMaxDynamicSharedMemorySize,
                         FOLD_SMEM_BYTES);

    semicrf_rowsum<<<8192, 256>>>(tr, tags, out);           // 65536 (b,e) warps
    semicrf_fold<<<64, 512, FOLD_SMEM_BYTES>>>(lens, out);  // one block per batch
}